// round 14
// baseline (speedup 1.0000x reference)
#include <cuda_runtime.h>
#include <math.h>

#define N_NODES 4096
#define NFEAT   128
#define NHID    128
#define NHEADS  4
#define NCLASS  32
#define KEDGE   32
#define ALPHA_LRELU 0.2f

// ---------------- scratch (no allocations allowed) ----------------
__device__ float g_h  [N_NODES * NHEADS * NHID];   // [n][head*128+d]
__device__ float g_xc [N_NODES * NHEADS * NHID];   // [n][head*128+d]
__device__ float g_f1p[2 * NHEADS * N_NODES];      // partial dots, slot = column-half
__device__ float g_f2p[2 * NHEADS * N_NODES];
__device__ int2  g_wj [N_NODES * NHEADS * KEDGE];  // {w_bits, j*512}, zero-padded
__device__ float g_h2 [N_NODES * NCLASS];
__device__ float g_f1o[N_NODES];
__device__ float g_f2o[N_NODES];

// ---------------- K1: h = x @ concat(Ws), fused partial f1/f2 ----------------
// pad-68 float4-LDS inner loop + fused epilogue (R13-proven)
__global__ void k_gemm1(const float* __restrict__ X, const float* __restrict__ Ws,
                        const float* __restrict__ a) {
    __shared__ __align__(16) float As[64][68];  // [k][m]
    __shared__ __align__(16) float Bs[64][68];  // [k][n]
    int bx = blockIdx.x;
    int by = blockIdx.y;
    int n0 = bx * 64;
    int head = n0 >> 7;
    int nloc = n0 & 127;
    int slot = bx & 1;
    const float* B = Ws + head * NFEAT * NHID;
    int m0 = by * 64;
    int tid = threadIdx.x;
    int tx = tid & 15, ty = tid >> 4;

    float acc[4][4] = {};
    for (int kc = 0; kc < NFEAT; kc += 64) {
        #pragma unroll
        for (int t = 0; t < 16; t++) {
            int e = t * 256 + tid;
            { int k = e & 63, m = e >> 6;
              As[k][m] = X[(m0 + m) * NFEAT + kc + k]; }
            { int n = e & 63, k = e >> 6;
              Bs[k][n] = B[(kc + k) * NHID + nloc + n]; }
        }
        __syncthreads();
        #pragma unroll 16
        for (int kk = 0; kk < 64; kk++) {
            float4 av4 = *(const float4*)&As[kk][ty * 4];
            float4 bv4 = *(const float4*)&Bs[kk][tx * 4];
            float av[4] = {av4.x, av4.y, av4.z, av4.w};
            float bv[4] = {bv4.x, bv4.y, bv4.z, bv4.w};
            #pragma unroll
            for (int i = 0; i < 4; i++)
                #pragma unroll
                for (int j = 0; j < 4; j++)
                    acc[i][j] += av[i] * bv[j];
        }
        __syncthreads();
    }
    float a1j[4], a2j[4];
    #pragma unroll
    for (int j = 0; j < 4; j++) {
        int col = nloc + tx * 4 + j;
        a1j[j] = a[head * 256 + col];
        a2j[j] = a[head * 256 + 128 + col];
    }
    #pragma unroll
    for (int i = 0; i < 4; i++) {
        int row = m0 + ty * 4 + i;
        float4 v = make_float4(acc[i][0], acc[i][1], acc[i][2], acc[i][3]);
        *(float4*)&g_h[(size_t)row * 512 + n0 + tx * 4] = v;
        float s1 = 0.f, s2 = 0.f;
        #pragma unroll
        for (int j = 0; j < 4; j++) { s1 += acc[i][j] * a1j[j]; s2 += acc[i][j] * a2j[j]; }
        #pragma unroll
        for (int o = 8; o; o >>= 1) {
            s1 += __shfl_xor_sync(0xffffffffu, s1, o);
            s2 += __shfl_xor_sync(0xffffffffu, s2, o);
        }
        if (tx == 0) {
            g_f1p[slot * 16384 + head * N_NODES + row] = s1;
            g_f2p[slot * 16384 + head * N_NODES + row] = s2;
        }
    }
}

// ---------------- K2: dedup + all-head softmax weights, packed {w, j*512} ------
// grid 1024, block 128: warp = row (R12-proven pattern)
__global__ void k_wgt(const int* __restrict__ edge) {
    int row  = blockIdx.x * 4 + (threadIdx.x >> 5);
    int lane = threadIdx.x & 31;
    int base = row & ~1023;

    int e = edge[row * KEDGE + lane];
    bool valid = (e >= 0);
    unsigned key = valid ? (unsigned)e : (0x40000000u + (unsigned)lane);
    unsigned grp = __match_any_sync(0xffffffffu, key);
    bool uniq = valid && ((__ffs(grp) - 1) == lane);
    int j = valid ? e : 0;

    #pragma unroll
    for (int head = 0; head < NHEADS; head++) {
        float f1 = g_f1p[head * N_NODES + row] + g_f1p[16384 + head * N_NODES + row];
        float p = 0.f;
        if (uniq) {
            float f2 = g_f2p[head * N_NODES + base + e] +
                       g_f2p[16384 + head * N_NODES + base + e];
            float t = f1 + f2;
            float la = (t > 0.f) ? t : ALPHA_LRELU * t;  // bounded: exp safe w/o max-sub
            p = __expf(la);
        }
        float s = p;
        #pragma unroll
        for (int o = 16; o; o >>= 1) s += __shfl_xor_sync(0xffffffffu, s, o);
        int2 v;
        v.x = __float_as_int(p / s);
        v.y = j * 512;                     // float-offset into g_h row space
        g_wj[(row * 4 + head) * KEDGE + lane] = v;
    }
}

// ---------------- K3: layer-1 aggregation, L1-tiled (no smem) -------------------
// grid (dc=4, head=4, part*4+rg=16) = 256 blocks, block 256 = 8 warps x 32 rows.
// Block working set: partition's 1024x32-float stripe = 128KB -> L1-resident.
__global__ void k_agg() {
    int dc   = blockIdx.x;
    int head = blockIdx.y;
    int part = blockIdx.z >> 2;
    int rg   = blockIdx.z & 3;
    int base = part << 10;
    int lane = threadIdx.x & 31, warp = threadIdx.x >> 5;
    int row0 = base + rg * 256 + warp * 32;

    const float* __restrict__ tl = g_h + (size_t)base * 512 + head * 128 + dc * 32 + lane;
    #pragma unroll 1
    for (int r = 0; r < 32; r += 2) {
        int rowA = row0 + r, rowB = rowA + 1;
        const int4* wjA = (const int4*)(g_wj + (rowA * 4 + head) * KEDGE);
        const int4* wjB = (const int4*)(g_wj + (rowB * 4 + head) * KEDGE);
        float aA = 0.f, aB = 0.f;
        #pragma unroll
        for (int k = 0; k < 16; k++) {
            int4 pA = wjA[k];              // uniform LDG.128: 2 (w, off) pairs
            int4 pB = wjB[k];
            aA += __int_as_float(pA.x) * tl[pA.y];   // coalesced 128B, L1-hot
            aA += __int_as_float(pA.z) * tl[pA.w];
            aB += __int_as_float(pB.x) * tl[pB.y];
            aB += __int_as_float(pB.z) * tl[pB.w];
        }
        float oA = aA > 0.f ? aA : expm1f(aA);
        float oB = aB > 0.f ? aB : expm1f(aB);
        g_xc[(size_t)rowA * 512 + head * 128 + dc * 32 + lane] = oA;
        g_xc[(size_t)rowB * 512 + head * 128 + dc * 32 + lane] = oB;
    }
}

// ---------------- K4: h2 = xc @ W_out, 0.5 LDS/FMA (R13-proven) -----------------
__global__ void k_gemm2(const float* __restrict__ W, const float* __restrict__ a_out) {
    __shared__ __align__(16) float  Xs[32][132];
    __shared__ __align__(16) float4 Wsm4[128][8];
    int r0   = blockIdx.x * 32;
    int tid  = threadIdx.x;
    int lane = tid & 31, warp = tid >> 5;
    int r    = lane >> 3;
    int c8   = lane & 7;
    int lrow = warp * 4 + r;

    float4 acc = make_float4(0.f, 0.f, 0.f, 0.f);
    for (int kc = 0; kc < 512; kc += 128) {
        #pragma unroll
        for (int t = 0; t < 4; t++) {
            int idx = tid + t * 256;
            { int rr = idx >> 5, cc = idx & 31;
              *(float4*)&Xs[rr][cc * 4] =
                  *(const float4*)&g_xc[(size_t)(r0 + rr) * 512 + kc + cc * 4]; }
            { int kk = idx >> 3, c = idx & 7;
              Wsm4[kk][c] = ((const float4*)W)[(kc + kk) * 8 + c]; }
        }
        __syncthreads();
        #pragma unroll 8
        for (int kk = 0; kk < 128; kk++) {
            float  xv = Xs[lrow][kk];
            float4 wv = Wsm4[kk][c8];
            acc.x += xv * wv.x; acc.y += xv * wv.y;
            acc.z += xv * wv.z; acc.w += xv * wv.w;
        }
        __syncthreads();
    }
    int row = r0 + lrow;
    *(float4*)&g_h2[row * 32 + c8 * 4] = acc;

    float4 a1 = *(const float4*)&a_out[c8 * 4];
    float4 a2 = *(const float4*)&a_out[32 + c8 * 4];
    float s1 = acc.x * a1.x + acc.y * a1.y + acc.z * a1.z + acc.w * a1.w;
    float s2 = acc.x * a2.x + acc.y * a2.y + acc.z * a2.z + acc.w * a2.w;
    #pragma unroll
    for (int o = 4; o; o >>= 1) {
        s1 += __shfl_xor_sync(0xffffffffu, s1, o);
        s2 += __shfl_xor_sync(0xffffffffu, s2, o);
    }
    if (c8 == 0) { g_f1o[row] = s1; g_f2o[row] = s2; }
}

// ---------------- K5: layer-2 attention + elu + log_softmax (inline dedup) ------
__global__ void k_attn2(const int* __restrict__ edge, float* __restrict__ out) {
    int row  = blockIdx.x * 4 + (threadIdx.x >> 5);
    int lane = threadIdx.x & 31;
    int base = row & ~1023;

    int e = edge[row * KEDGE + lane];
    bool valid = (e >= 0);
    unsigned key = valid ? (unsigned)e : (0x40000000u + (unsigned)lane);
    unsigned grp = __match_any_sync(0xffffffffu, key);
    bool uniq = valid && ((__ffs(grp) - 1) == lane);

    float p = 0.f;
    if (uniq) {
        float t = g_f1o[row] + g_f2o[base + e];
        float la = (t > 0.f) ? t : ALPHA_LRELU * t;
        p = __expf(la);
    }
    float s = p;
    #pragma unroll
    for (int o = 16; o; o >>= 1) s += __shfl_xor_sync(0xffffffffu, s, o);
    float wgt = p / s;
    int j = valid ? e : 0;

    float acc = 0.f;
    #pragma unroll 8
    for (int k = 0; k < KEDGE; k++) {
        float wk = __shfl_sync(0xffffffffu, wgt, k);
        int   jk = __shfl_sync(0xffffffffu, j, k);
        acc += wk * g_h2[(base + jk) * 32 + lane];
    }
    float v = acc > 0.f ? acc : expm1f(acc);
    float m2 = v;
    #pragma unroll
    for (int o = 16; o; o >>= 1) m2 = fmaxf(m2, __shfl_xor_sync(0xffffffffu, m2, o));
    float se = __expf(v - m2);
    #pragma unroll
    for (int o = 16; o; o >>= 1) se += __shfl_xor_sync(0xffffffffu, se, o);
    out[row * 32 + lane] = v - m2 - logf(se);
}

// ---------------- launch ----------------
extern "C" void kernel_launch(void* const* d_in, const int* in_sizes, int n_in,
                              void* d_out, int out_size) {
    const float* x     = (const float*)d_in[0];
    const int*   edge  = (const int*)d_in[1];
    const float* Ws    = (const float*)d_in[3];
    const float* a     = (const float*)d_in[4];
    const float* W_out = (const float*)d_in[5];
    const float* a_out = (const float*)d_in[6];
    float* out = (float*)d_out;

    dim3 g1(8, 64);
    k_gemm1<<<g1, 256>>>(x, Ws, a);
    k_wgt<<<N_NODES / 4, 128>>>(edge);
    dim3 ga(4, 4, 16);
    k_agg<<<ga, 256>>>();
    k_gemm2<<<128, 256>>>(W_out, a_out);
    k_attn2<<<N_NODES / 4, 128>>>(edge, out);
}

// round 15
// speedup vs baseline: 1.4744x; 1.4744x over previous
#include <cuda_runtime.h>
#include <math.h>

#define N_NODES 4096
#define NFEAT   128
#define NHID    128
#define NHEADS  4
#define NCLASS  32
#define KEDGE   32
#define ALPHA_LRELU 0.2f

// ---------------- scratch (no allocations allowed) ----------------
__device__ float g_h  [N_NODES * NHEADS * NHID];   // [n][head*128+d]
__device__ float g_xc [N_NODES * NHEADS * NHID];   // [n][head*128+d]
__device__ float g_f1p[2 * NHEADS * N_NODES];      // partial dots, slot = column-half
__device__ float g_f2p[2 * NHEADS * N_NODES];
__device__ int2  g_wj [N_NODES * NHEADS * KEDGE];  // {w_bits, j*512}, zero-padded
__device__ int   g_cnt[N_NODES];
__device__ float g_h2 [N_NODES * NCLASS];
__device__ float g_f1o[N_NODES];
__device__ float g_f2o[N_NODES];

// ---------------- K1: h = x @ concat(Ws), fused partial f1/f2 (R13-proven) ------
__global__ void k_gemm1(const float* __restrict__ X, const float* __restrict__ Ws,
                        const float* __restrict__ a) {
    __shared__ __align__(16) float As[64][68];  // [k][m]
    __shared__ __align__(16) float Bs[64][68];  // [k][n]
    int bx = blockIdx.x;
    int by = blockIdx.y;
    int n0 = bx * 64;
    int head = n0 >> 7;
    int nloc = n0 & 127;
    int slot = bx & 1;
    const float* B = Ws + head * NFEAT * NHID;
    int m0 = by * 64;
    int tid = threadIdx.x;
    int tx = tid & 15, ty = tid >> 4;

    float acc[4][4] = {};
    for (int kc = 0; kc < NFEAT; kc += 64) {
        #pragma unroll
        for (int t = 0; t < 16; t++) {
            int e = t * 256 + tid;
            { int k = e & 63, m = e >> 6;
              As[k][m] = X[(m0 + m) * NFEAT + kc + k]; }
            { int n = e & 63, k = e >> 6;
              Bs[k][n] = B[(kc + k) * NHID + nloc + n]; }
        }
        __syncthreads();
        #pragma unroll 16
        for (int kk = 0; kk < 64; kk++) {
            float4 av4 = *(const float4*)&As[kk][ty * 4];
            float4 bv4 = *(const float4*)&Bs[kk][tx * 4];
            float av[4] = {av4.x, av4.y, av4.z, av4.w};
            float bv[4] = {bv4.x, bv4.y, bv4.z, bv4.w};
            #pragma unroll
            for (int i = 0; i < 4; i++)
                #pragma unroll
                for (int j = 0; j < 4; j++)
                    acc[i][j] += av[i] * bv[j];
        }
        __syncthreads();
    }
    float a1j[4], a2j[4];
    #pragma unroll
    for (int j = 0; j < 4; j++) {
        int col = nloc + tx * 4 + j;
        a1j[j] = a[head * 256 + col];
        a2j[j] = a[head * 256 + 128 + col];
    }
    #pragma unroll
    for (int i = 0; i < 4; i++) {
        int row = m0 + ty * 4 + i;
        float4 v = make_float4(acc[i][0], acc[i][1], acc[i][2], acc[i][3]);
        *(float4*)&g_h[(size_t)row * 512 + n0 + tx * 4] = v;
        float s1 = 0.f, s2 = 0.f;
        #pragma unroll
        for (int j = 0; j < 4; j++) { s1 += acc[i][j] * a1j[j]; s2 += acc[i][j] * a2j[j]; }
        #pragma unroll
        for (int o = 8; o; o >>= 1) {
            s1 += __shfl_xor_sync(0xffffffffu, s1, o);
            s2 += __shfl_xor_sync(0xffffffffu, s2, o);
        }
        if (tx == 0) {
            g_f1p[slot * 16384 + head * N_NODES + row] = s1;
            g_f2p[slot * 16384 + head * N_NODES + row] = s2;
        }
    }
}

// ---------------- K2: dedup + all-head softmax weights + cnt --------------------
// grid 1024, block 128: warp = row (R12-proven pattern)
__global__ void k_wgt(const int* __restrict__ edge) {
    int row  = blockIdx.x * 4 + (threadIdx.x >> 5);
    int lane = threadIdx.x & 31;
    int base = row & ~1023;

    int e = edge[row * KEDGE + lane];
    bool valid = (e >= 0);
    unsigned key = valid ? (unsigned)e : (0x40000000u + (unsigned)lane);
    unsigned grp = __match_any_sync(0xffffffffu, key);
    bool uniq = valid && ((__ffs(grp) - 1) == lane);
    unsigned bal = __ballot_sync(0xffffffffu, uniq);
    int cnt = __popc(bal);
    // compact unique neighbors to the front so cnt-bounded loops work
    int pos = __popc(bal & ((1u << lane) - 1u));   // rank among uniq lanes
    if (lane == 0) g_cnt[row] = cnt;

    #pragma unroll
    for (int head = 0; head < NHEADS; head++) {
        float f1 = g_f1p[head * N_NODES + row] + g_f1p[16384 + head * N_NODES + row];
        float p = 0.f;
        if (uniq) {
            float f2 = g_f2p[head * N_NODES + base + e] +
                       g_f2p[16384 + head * N_NODES + base + e];
            float t = f1 + f2;
            float la = (t > 0.f) ? t : ALPHA_LRELU * t;  // bounded: exp safe w/o max-sub
            p = __expf(la);
        }
        float s = p;
        #pragma unroll
        for (int o = 16; o; o >>= 1) s += __shfl_xor_sync(0xffffffffu, s, o);
        int2* dst = g_wj + (row * 4 + head) * KEDGE;
        // zero the tail (pairs beyond cnt, incl. odd-pad slot) then scatter uniq
        int2 zero; zero.x = 0; zero.y = 0;
        if (lane >= cnt) dst[lane] = zero;
        if (uniq) {
            int2 v;
            v.x = __float_as_int(p / s);
            v.y = e * 512;                 // float-offset into g_h row space
            dst[pos] = v;
        }
    }
}

// ---------------- K3: layer-1 sparse attention + elu (packed-wj inner loop) -----
// grid 4096, block 128: warp = head, lane = d/4. Same gather pattern as R13.
__global__ void k_attn1() {
    int row  = blockIdx.x;
    int head = threadIdx.x >> 5;
    int lane = threadIdx.x & 31;
    int base = row & ~1023;
    int npair = (g_cnt[row] + 1) >> 1;     // int4 loads cover 2 neighbors each

    const float* tl = g_h + (size_t)base * 512 + head * 128 + lane * 4;
    const int4* wj = (const int4*)(g_wj + (row * 4 + head) * KEDGE);

    float4 acc = make_float4(0.f, 0.f, 0.f, 0.f);
    for (int k = 0; k < npair; k++) {
        int4 p = wj[k];                    // uniform LDG.128: {w0, off0, w1, off1}
        float w0 = __int_as_float(p.x);
        float w1 = __int_as_float(p.z);
        float4 h0 = *(const float4*)&tl[p.y];
        float4 h1 = *(const float4*)&tl[p.w];
        acc.x += w0 * h0.x + w1 * h1.x;
        acc.y += w0 * h0.y + w1 * h1.y;
        acc.z += w0 * h0.z + w1 * h1.z;
        acc.w += w0 * h0.w + w1 * h1.w;
    }
    float4 o4;
    o4.x = acc.x > 0.f ? acc.x : expm1f(acc.x);
    o4.y = acc.y > 0.f ? acc.y : expm1f(acc.y);
    o4.z = acc.z > 0.f ? acc.z : expm1f(acc.z);
    o4.w = acc.w > 0.f ? acc.w : expm1f(acc.w);
    *(float4*)&g_xc[(size_t)row * 512 + head * 128 + lane * 4] = o4;
}

// ---------------- K4: h2 = xc @ W_out, 0.5 LDS/FMA (R13-proven) -----------------
__global__ void k_gemm2(const float* __restrict__ W, const float* __restrict__ a_out) {
    __shared__ __align__(16) float  Xs[32][132];
    __shared__ __align__(16) float4 Wsm4[128][8];
    int r0   = blockIdx.x * 32;
    int tid  = threadIdx.x;
    int lane = tid & 31, warp = tid >> 5;
    int r    = lane >> 3;
    int c8   = lane & 7;
    int lrow = warp * 4 + r;

    float4 acc = make_float4(0.f, 0.f, 0.f, 0.f);
    for (int kc = 0; kc < 512; kc += 128) {
        #pragma unroll
        for (int t = 0; t < 4; t++) {
            int idx = tid + t * 256;
            { int rr = idx >> 5, cc = idx & 31;
              *(float4*)&Xs[rr][cc * 4] =
                  *(const float4*)&g_xc[(size_t)(r0 + rr) * 512 + kc + cc * 4]; }
            { int kk = idx >> 3, c = idx & 7;
              Wsm4[kk][c] = ((const float4*)W)[(kc + kk) * 8 + c]; }
        }
        __syncthreads();
        #pragma unroll 8
        for (int kk = 0; kk < 128; kk++) {
            float  xv = Xs[lrow][kk];
            float4 wv = Wsm4[kk][c8];
            acc.x += xv * wv.x; acc.y += xv * wv.y;
            acc.z += xv * wv.z; acc.w += xv * wv.w;
        }
        __syncthreads();
    }
    int row = r0 + lrow;
    *(float4*)&g_h2[row * 32 + c8 * 4] = acc;

    float4 a1 = *(const float4*)&a_out[c8 * 4];
    float4 a2 = *(const float4*)&a_out[32 + c8 * 4];
    float s1 = acc.x * a1.x + acc.y * a1.y + acc.z * a1.z + acc.w * a1.w;
    float s2 = acc.x * a2.x + acc.y * a2.y + acc.z * a2.z + acc.w * a2.w;
    #pragma unroll
    for (int o = 4; o; o >>= 1) {
        s1 += __shfl_xor_sync(0xffffffffu, s1, o);
        s2 += __shfl_xor_sync(0xffffffffu, s2, o);
    }
    if (c8 == 0) { g_f1o[row] = s1; g_f2o[row] = s2; }
}

// ---------------- K5: layer-2 attention + elu + log_softmax (inline dedup) ------
__global__ void k_attn2(const int* __restrict__ edge, float* __restrict__ out) {
    int row  = blockIdx.x * 4 + (threadIdx.x >> 5);
    int lane = threadIdx.x & 31;
    int base = row & ~1023;

    int e = edge[row * KEDGE + lane];
    bool valid = (e >= 0);
    unsigned key = valid ? (unsigned)e : (0x40000000u + (unsigned)lane);
    unsigned grp = __match_any_sync(0xffffffffu, key);
    bool uniq = valid && ((__ffs(grp) - 1) == lane);

    float p = 0.f;
    if (uniq) {
        float t = g_f1o[row] + g_f2o[base + e];
        float la = (t > 0.f) ? t : ALPHA_LRELU * t;
        p = __expf(la);
    }
    float s = p;
    #pragma unroll
    for (int o = 16; o; o >>= 1) s += __shfl_xor_sync(0xffffffffu, s, o);
    float wgt = p / s;
    int j = valid ? e : 0;

    float acc = 0.f;
    #pragma unroll 8
    for (int k = 0; k < KEDGE; k++) {
        float wk = __shfl_sync(0xffffffffu, wgt, k);
        int   jk = __shfl_sync(0xffffffffu, j, k);
        acc += wk * g_h2[(base + jk) * 32 + lane];
    }
    float v = acc > 0.f ? acc : expm1f(acc);
    float m2 = v;
    #pragma unroll
    for (int o = 16; o; o >>= 1) m2 = fmaxf(m2, __shfl_xor_sync(0xffffffffu, m2, o));
    float se = __expf(v - m2);
    #pragma unroll
    for (int o = 16; o; o >>= 1) se += __shfl_xor_sync(0xffffffffu, se, o);
    out[row * 32 + lane] = v - m2 - logf(se);
}

// ---------------- launch ----------------
extern "C" void kernel_launch(void* const* d_in, const int* in_sizes, int n_in,
                              void* d_out, int out_size) {
    const float* x     = (const float*)d_in[0];
    const int*   edge  = (const int*)d_in[1];
    const float* Ws    = (const float*)d_in[3];
    const float* a     = (const float*)d_in[4];
    const float* W_out = (const float*)d_in[5];
    const float* a_out = (const float*)d_in[6];
    float* out = (float*)d_out;

    dim3 g1(8, 64);
    k_gemm1<<<g1, 256>>>(x, Ws, a);
    k_wgt<<<N_NODES / 4, 128>>>(edge);
    k_attn1<<<N_NODES, 128>>>();
    k_gemm2<<<128, 256>>>(W_out, a_out);
    k_attn2<<<N_NODES / 4, 128>>>(edge, out);
}

// round 16
// speedup vs baseline: 1.6571x; 1.1239x over previous
#include <cuda_runtime.h>
#include <math.h>

#define N_NODES 4096
#define NFEAT   128
#define NHID    128
#define NHEADS  4
#define NCLASS  32
#define KEDGE   32
#define ALPHA_LRELU 0.2f

// ---------------- scratch (no allocations allowed) ----------------
__device__ float g_h  [N_NODES * NHEADS * NHID];   // [n][head*128+d]
__device__ float g_xc [N_NODES * NHEADS * NHID];   // [n][head*128+d]
__device__ float g_f1p[2 * NHEADS * N_NODES];      // partial dots, slot = column-half
__device__ float g_f2p[2 * NHEADS * N_NODES];
__device__ float g_h2 [N_NODES * NCLASS];
__device__ float g_f1o[N_NODES];
__device__ float g_f2o[N_NODES];
__device__ int   g_cnt[N_NODES];
__device__ int   g_nbr[N_NODES * KEDGE];

// ---------------- K1: dedup neighbor lists (j=0 padding beyond cnt) ------------
__global__ void k_nbrs(const int* __restrict__ edge) {
    int row  = blockIdx.x * 4 + (threadIdx.x >> 5);
    int lane = threadIdx.x & 31;
    int e = edge[row * KEDGE + lane];
    bool valid = (e >= 0);
    unsigned key = valid ? (unsigned)e : (0x40000000u + (unsigned)lane);
    unsigned grp = __match_any_sync(0xffffffffu, key);
    bool uniq = valid && ((__ffs(grp) - 1) == lane);
    unsigned bal = __ballot_sync(0xffffffffu, uniq);
    int cnt = __popc(bal);
    // init all slots to 0 so padded gathers hit a fixed hot line
    g_nbr[row * KEDGE + lane] = 0;
    __syncwarp();
    if (uniq) {
        int pos = __popc(bal & ((1u << lane) - 1u));
        g_nbr[row * KEDGE + pos] = e;
    }
    if (lane == 0) g_cnt[row] = cnt;
}

// ---------------- K2: h = x @ concat(Ws), fused partial f1/f2 (R13-proven) -----
__global__ void k_gemm1(const float* __restrict__ X, const float* __restrict__ Ws,
                        const float* __restrict__ a) {
    __shared__ __align__(16) float As[64][68];  // [k][m]
    __shared__ __align__(16) float Bs[64][68];  // [k][n]
    int bx = blockIdx.x;
    int by = blockIdx.y;
    int n0 = bx * 64;
    int head = n0 >> 7;
    int nloc = n0 & 127;
    int slot = bx & 1;
    const float* B = Ws + head * NFEAT * NHID;
    int m0 = by * 64;
    int tid = threadIdx.x;
    int tx = tid & 15, ty = tid >> 4;

    float acc[4][4] = {};
    for (int kc = 0; kc < NFEAT; kc += 64) {
        #pragma unroll
        for (int t = 0; t < 16; t++) {
            int e = t * 256 + tid;
            { int k = e & 63, m = e >> 6;
              As[k][m] = X[(m0 + m) * NFEAT + kc + k]; }
            { int n = e & 63, k = e >> 6;
              Bs[k][n] = B[(kc + k) * NHID + nloc + n]; }
        }
        __syncthreads();
        #pragma unroll 16
        for (int kk = 0; kk < 64; kk++) {
            float4 av4 = *(const float4*)&As[kk][ty * 4];
            float4 bv4 = *(const float4*)&Bs[kk][tx * 4];
            float av[4] = {av4.x, av4.y, av4.z, av4.w};
            float bv[4] = {bv4.x, bv4.y, bv4.z, bv4.w};
            #pragma unroll
            for (int i = 0; i < 4; i++)
                #pragma unroll
                for (int j = 0; j < 4; j++)
                    acc[i][j] += av[i] * bv[j];
        }
        __syncthreads();
    }
    float a1j[4], a2j[4];
    #pragma unroll
    for (int j = 0; j < 4; j++) {
        int col = nloc + tx * 4 + j;
        a1j[j] = a[head * 256 + col];
        a2j[j] = a[head * 256 + 128 + col];
    }
    #pragma unroll
    for (int i = 0; i < 4; i++) {
        int row = m0 + ty * 4 + i;
        float4 v = make_float4(acc[i][0], acc[i][1], acc[i][2], acc[i][3]);
        *(float4*)&g_h[(size_t)row * 512 + n0 + tx * 4] = v;
        float s1 = 0.f, s2 = 0.f;
        #pragma unroll
        for (int j = 0; j < 4; j++) { s1 += acc[i][j] * a1j[j]; s2 += acc[i][j] * a2j[j]; }
        #pragma unroll
        for (int o = 8; o; o >>= 1) {
            s1 += __shfl_xor_sync(0xffffffffu, s1, o);
            s2 += __shfl_xor_sync(0xffffffffu, s2, o);
        }
        if (tx == 0) {
            g_f1p[slot * 16384 + head * N_NODES + row] = s1;
            g_f2p[slot * 16384 + head * N_NODES + row] = s2;
        }
    }
}

// ---------------- K3: layer-1 sparse attention + elu (fixed-32 gather loop) ----
__global__ void k_attn1() {
    int row  = blockIdx.x;
    int head = threadIdx.x >> 5;
    int lane = threadIdx.x & 31;
    int base = row & ~1023;
    int cnt  = g_cnt[row];

    float f1 = g_f1p[head * N_NODES + row] + g_f1p[16384 + head * N_NODES + row];

    int j = g_nbr[row * KEDGE + lane];     // 0 for padding lanes
    float e = -INFINITY;
    if (lane < cnt) {
        float f2 = g_f2p[head * N_NODES + base + j] +
                   g_f2p[16384 + head * N_NODES + base + j];
        float t = f1 + f2;
        e = (t > 0.f) ? t : ALPHA_LRELU * t;
    }
    float m = e;
    #pragma unroll
    for (int o = 16; o; o >>= 1) m = fmaxf(m, __shfl_xor_sync(0xffffffffu, m, o));
    float p = (lane < cnt) ? __expf(e - m) : 0.f;
    float s = p;
    #pragma unroll
    for (int o = 16; o; o >>= 1) s += __shfl_xor_sync(0xffffffffu, s, o);
    float wgt = p / s;                     // 0 for padding lanes

    const float* tl = g_h + (size_t)base * 512 + head * 128 + lane * 4;
    float4 acc = make_float4(0.f, 0.f, 0.f, 0.f);
    // FIXED trip count: padding iterations contribute 0 * h[base+0] (exact).
    // Compile-time bound lets ptxas front-batch SHFLs + LDGs -> high MLP.
    #pragma unroll
    for (int k = 0; k < KEDGE; k++) {
        float wk = __shfl_sync(0xffffffffu, wgt, k);
        int   jk = __shfl_sync(0xffffffffu, j, k);
        float4 hv = *(const float4*)&tl[jk * 512];
        acc.x += wk * hv.x; acc.y += wk * hv.y;
        acc.z += wk * hv.z; acc.w += wk * hv.w;
    }
    float4 o4;
    o4.x = acc.x > 0.f ? acc.x : expm1f(acc.x);
    o4.y = acc.y > 0.f ? acc.y : expm1f(acc.y);
    o4.z = acc.z > 0.f ? acc.z : expm1f(acc.z);
    o4.w = acc.w > 0.f ? acc.w : expm1f(acc.w);
    *(float4*)&g_xc[(size_t)row * 512 + head * 128 + lane * 4] = o4;
}

// ---------------- K4: h2 = xc @ W_out, 0.5 LDS/FMA (R13-proven) -----------------
__global__ void k_gemm2(const float* __restrict__ W, const float* __restrict__ a_out) {
    __shared__ __align__(16) float  Xs[32][132];
    __shared__ __align__(16) float4 Wsm4[128][8];
    int r0   = blockIdx.x * 32;
    int tid  = threadIdx.x;
    int lane = tid & 31, warp = tid >> 5;
    int r    = lane >> 3;
    int c8   = lane & 7;
    int lrow = warp * 4 + r;

    float4 acc = make_float4(0.f, 0.f, 0.f, 0.f);
    for (int kc = 0; kc < 512; kc += 128) {
        #pragma unroll
        for (int t = 0; t < 4; t++) {
            int idx = tid + t * 256;
            { int rr = idx >> 5, cc = idx & 31;
              *(float4*)&Xs[rr][cc * 4] =
                  *(const float4*)&g_xc[(size_t)(r0 + rr) * 512 + kc + cc * 4]; }
            { int kk = idx >> 3, c = idx & 7;
              Wsm4[kk][c] = ((const float4*)W)[(kc + kk) * 8 + c]; }
        }
        __syncthreads();
        #pragma unroll 8
        for (int kk = 0; kk < 128; kk++) {
            float  xv = Xs[lrow][kk];
            float4 wv = Wsm4[kk][c8];
            acc.x += xv * wv.x; acc.y += xv * wv.y;
            acc.z += xv * wv.z; acc.w += xv * wv.w;
        }
        __syncthreads();
    }
    int row = r0 + lrow;
    *(float4*)&g_h2[row * 32 + c8 * 4] = acc;

    float4 a1 = *(const float4*)&a_out[c8 * 4];
    float4 a2 = *(const float4*)&a_out[32 + c8 * 4];
    float s1 = acc.x * a1.x + acc.y * a1.y + acc.z * a1.z + acc.w * a1.w;
    float s2 = acc.x * a2.x + acc.y * a2.y + acc.z * a2.z + acc.w * a2.w;
    #pragma unroll
    for (int o = 4; o; o >>= 1) {
        s1 += __shfl_xor_sync(0xffffffffu, s1, o);
        s2 += __shfl_xor_sync(0xffffffffu, s2, o);
    }
    if (c8 == 0) { g_f1o[row] = s1; g_f2o[row] = s2; }
}

// ---------------- K5: layer-2 attention + elu + log_softmax ----------------
__global__ void k_attn2(float* __restrict__ out) {
    int row  = blockIdx.x * 4 + (threadIdx.x >> 5);
    int lane = threadIdx.x & 31;
    int base = row & ~1023;
    int cnt  = g_cnt[row];

    int j = g_nbr[row * KEDGE + lane];
    float e = -INFINITY;
    if (lane < cnt) {
        float t = g_f1o[row] + g_f2o[base + j];
        e = (t > 0.f) ? t : ALPHA_LRELU * t;
    }
    float m = e;
    #pragma unroll
    for (int o = 16; o; o >>= 1) m = fmaxf(m, __shfl_xor_sync(0xffffffffu, m, o));
    float p = (lane < cnt) ? __expf(e - m) : 0.f;
    float s = p;
    #pragma unroll
    for (int o = 16; o; o >>= 1) s += __shfl_xor_sync(0xffffffffu, s, o);
    float wgt = p / s;

    float acc = 0.f;
    #pragma unroll
    for (int k = 0; k < KEDGE; k++) {
        float wk = __shfl_sync(0xffffffffu, wgt, k);
        int   jk = __shfl_sync(0xffffffffu, j, k);
        acc += wk * g_h2[(base + jk) * 32 + lane];
    }
    float v = acc > 0.f ? acc : expm1f(acc);
    float m2 = v;
    #pragma unroll
    for (int o = 16; o; o >>= 1) m2 = fmaxf(m2, __shfl_xor_sync(0xffffffffu, m2, o));
    float se = __expf(v - m2);
    #pragma unroll
    for (int o = 16; o; o >>= 1) se += __shfl_xor_sync(0xffffffffu, se, o);
    out[row * 32 + lane] = v - m2 - logf(se);
}

// ---------------- launch ----------------
extern "C" void kernel_launch(void* const* d_in, const int* in_sizes, int n_in,
                              void* d_out, int out_size) {
    const float* x     = (const float*)d_in[0];
    const int*   edge  = (const int*)d_in[1];
    const float* Ws    = (const float*)d_in[3];
    const float* a     = (const float*)d_in[4];
    const float* W_out = (const float*)d_in[5];
    const float* a_out = (const float*)d_in[6];
    float* out = (float*)d_out;

    k_nbrs<<<N_NODES / 4, 128>>>(edge);
    dim3 g1(8, 64);
    k_gemm1<<<g1, 256>>>(x, Ws, a);
    k_attn1<<<N_NODES, 128>>>();
    k_gemm2<<<128, 256>>>(W_out, a_out);
    k_attn2<<<N_NODES / 4, 128>>>(out);
}